// round 8
// baseline (speedup 1.0000x reference)
#include <cuda_runtime.h>
#include <cuda_bf16.h>
#include <cuda_fp8.h>
#include <cstdint>

// ===========================================================================
// NT-Xent (SimCLR) loss, B=4096, D=256, T=0.5  ->  N=8192 rows, K=256.
//
// R7: FP8 (e4m3) similarity GEMM via mma.sync.m16n8k32.f32.e4m3.e4m3.f32
// (standard PTX since sm_89 -- compiles on plain compute_103, unlike tcgen05).
// 2x MACs per instruction vs bf16 k16; tile bytes halve (64KB/tile), chunks
// 4 -> 2, LDSM count halves. Fragment byte-layouts match bf16-k16 at 16B
// granularity, so ldmatrix addressing and swizzle are unchanged.
//
// Triangle trick: exp(2*sim) symmetric -> 2080 upper 128x128 tiles; off-diag
// tiles emit row-sums AND col-sums. Logit scale folded into inputs
// (zb = z_hat * sqrt(2*log2 e)) so epilogue exp = bare ex2.approx.
// pos/diag recomputed in fp32 from the SAME fp8-decoded values the MMA saw,
// so the diagonal subtraction cancels to rounding.
// ===========================================================================

#define N_TOTAL 8192
#define DK      256
#define TILE    128
#define NTILES  64
#define NSLOTS  (NTILES * 2)                    // 128 partial slots per row
#define NTRI    (NTILES * (NTILES + 1) / 2)     // 2080 triangle tiles

#define SCALE_S 1.6986435987381852f             // sqrt(2*log2(e))

__device__ uint8_t g_zb8[(size_t)N_TOTAL * DK];             // 2 MB, e4m3
__device__ float g_rowpart[(size_t)N_TOTAL * NSLOTS];       // 4 MB
__device__ float g_partial[1024];
__device__ int   g_done;

// ---------------------------------------------------------------------------
__device__ __forceinline__ uint32_t smem_u32(const void* p) {
    uint32_t a;
    asm("{ .reg .u64 t; cvta.to.shared.u64 t, %1; cvt.u32.u64 %0, t; }"
        : "=r"(a) : "l"(p));
    return a;
}

__device__ __forceinline__ float fast_exp2(float x) {
    float y;
    asm("ex2.approx.f32 %0, %1;" : "=f"(y) : "f"(x));
    return y;
}

__device__ __forceinline__ float fp8_to_f32(uint8_t b) {
    __half_raw h = __nv_cvt_fp8_to_halfraw(b, __NV_E4M3);
    return __half2float(*reinterpret_cast<__half*>(&h));
}

#define LDSM_X4(r, addr) \
    asm volatile("ldmatrix.sync.aligned.m8n8.x4.shared.b16 {%0,%1,%2,%3}, [%4];" \
        : "=r"((r)[0]), "=r"((r)[1]), "=r"((r)[2]), "=r"((r)[3]) : "r"(addr))

#define MMA16832(c, a, b0v, b1v) \
    asm volatile("mma.sync.aligned.m16n8k32.row.col.f32.e4m3.e4m3.f32 " \
        "{%0,%1,%2,%3}, {%4,%5,%6,%7}, {%8,%9}, {%0,%1,%2,%3};" \
        : "+f"((c)[0]), "+f"((c)[1]), "+f"((c)[2]), "+f"((c)[3]) \
        : "r"((a)[0]), "r"((a)[1]), "r"((a)[2]), "r"((a)[3]), \
          "r"(b0v), "r"(b1v))

__device__ __forceinline__ void cp16(uint32_t saddr, const void* gptr) {
    uint64_t g;
    asm volatile("cvta.to.global.u64 %0, %1;" : "=l"(g) : "l"(gptr));
    asm volatile("cp.async.cg.shared.global [%0], [%1], 16;"
                 :: "r"(saddr), "l"(g) : "memory");
}
template <int N>
__device__ __forceinline__ void cp_wait() {
    asm volatile("cp.async.wait_group %0;" :: "n"(N) : "memory");
}
__device__ __forceinline__ void cp_commit() {
    asm volatile("cp.async.commit_group;" ::: "memory");
}

// ---------------------------------------------------------------------------
// Kernel 1: normalize rows -> e4m3 (pre-scaled by SCALE_S), reset done ctr.
// 2 x float4 loads + 8B fp8 store per lane.
// ---------------------------------------------------------------------------
__global__ __launch_bounds__(256) void normalize_kernel(
    const float* __restrict__ zi, const float* __restrict__ zj)
{
    if (blockIdx.x == 0 && threadIdx.x == 0) g_done = 0;
    int row  = blockIdx.x * 8 + (threadIdx.x >> 5);
    int lane = threadIdx.x & 31;
    const float* src = (row < 4096) ? zi + (size_t)row * DK
                                    : zj + (size_t)(row - 4096) * DK;
    float4 v0 = reinterpret_cast<const float4*>(src)[lane * 2];
    float4 v1 = reinterpret_cast<const float4*>(src)[lane * 2 + 1];
    float ss = v0.x * v0.x + v0.y * v0.y + v0.z * v0.z + v0.w * v0.w
             + v1.x * v1.x + v1.y * v1.y + v1.z * v1.z + v1.w * v1.w;
    #pragma unroll
    for (int o = 16; o; o >>= 1) ss += __shfl_xor_sync(0xffffffffu, ss, o);
    float rn = rsqrtf(ss) * SCALE_S;

    __nv_fp8x2_storage_t q0 = __nv_cvt_float2_to_fp8x2(
        make_float2(v0.x * rn, v0.y * rn), __NV_SATFINITE, __NV_E4M3);
    __nv_fp8x2_storage_t q1 = __nv_cvt_float2_to_fp8x2(
        make_float2(v0.z * rn, v0.w * rn), __NV_SATFINITE, __NV_E4M3);
    __nv_fp8x2_storage_t q2 = __nv_cvt_float2_to_fp8x2(
        make_float2(v1.x * rn, v1.y * rn), __NV_SATFINITE, __NV_E4M3);
    __nv_fp8x2_storage_t q3 = __nv_cvt_float2_to_fp8x2(
        make_float2(v1.z * rn, v1.w * rn), __NV_SATFINITE, __NV_E4M3);
    uint2 o2;
    o2.x = (uint32_t)q0 | ((uint32_t)q1 << 16);
    o2.y = (uint32_t)q2 | ((uint32_t)q3 << 16);
    reinterpret_cast<uint2*>(g_zb8 + (size_t)row * DK)[lane] = o2;
}

// ---------------------------------------------------------------------------
// Kernel 2: upper-triangle 128x128 FP8 MMA tiles + exp row/col sums.
// 1D grid of 2080 CTAs; CTA t -> tile (x, y), y >= x.
// 256 threads (8 warps, 4(M) x 2(N), warp tile 32x64).
// K=256 (256B rows) in 2 chunks of 128B via 2-stage cp.async (32KB smem).
// ---------------------------------------------------------------------------
#define KCHUNK_B    128                          // bytes (=elements) per chunk
#define MAT_BYTES   (TILE * KCHUNK_B)            // 16384
#define STAGE_BYTES (2 * MAT_BYTES)              // 32768
#define CW_OFF      (2 * STAGE_BYTES)            // 65536
#define SMEM_BYTES  (CW_OFF + 2048)              // 67584

// swizzled byte offset within a [128 x 128B] chunk: row r, 16B-group kg(0..7)
__device__ __forceinline__ uint32_t sw_off(int r, int kg) {
    return (uint32_t)(r * 128 + ((kg ^ (r & 7)) << 4));
}

__device__ __forceinline__ void prefetch_chunk(
    uint32_t sbase, int stage, int row0, int col0, int chunk, int tid)
{
    #pragma unroll
    for (int i = 0; i < 8; ++i) {
        int v   = tid + i * 256;         // 0..2047
        int mat = v >> 10;               // 0 = A, 1 = B
        int r   = (v >> 3) & 127;
        int kg  = v & 7;
        int grow = (mat ? col0 : row0) + r;
        const uint8_t* g = g_zb8 + (size_t)grow * DK + chunk * KCHUNK_B + kg * 16;
        uint32_t s = sbase + stage * STAGE_BYTES + mat * MAT_BYTES + sw_off(r, kg);
        cp16(s, g);
    }
    cp_commit();
}

__global__ __launch_bounds__(256, 2) void simexp_kernel() {
    extern __shared__ char smem[];
    const uint32_t sbase = smem_u32(smem);
    const int tid  = threadIdx.x;
    const int warp = tid >> 5;
    const int lane = tid & 31;

    // --- decode linear tile id -> (x, y) with y >= x ---
    const int t = blockIdx.x;
    int x = __float2int_rd((129.0f - sqrtf(16641.0f - 8.0f * (float)t)) * 0.5f);
    if (x > 63) x = 63;
    while (x > 0 && x * (129 - x) / 2 > t) --x;
    while ((x + 1) * (129 - (x + 1)) / 2 <= t) ++x;
    const int y = x + (t - x * (129 - x) / 2);

    const int row0 = x * TILE;
    const int col0 = y * TILE;
    const int warp_m = (warp >> 1) * 32;
    const int warp_n = (warp & 1) * 64;

    float acc[2][8][4];
    #pragma unroll
    for (int mf = 0; mf < 2; ++mf)
        #pragma unroll
        for (int nf = 0; nf < 8; ++nf)
            #pragma unroll
            for (int q = 0; q < 4; ++q) acc[mf][nf][q] = 0.f;

    prefetch_chunk(sbase, 0, row0, col0, 0, tid);

    #pragma unroll
    for (int c = 0; c < 2; ++c) {
        if (c == 0) {
            prefetch_chunk(sbase, 1, row0, col0, 1, tid);
            cp_wait<1>();
        } else {
            cp_wait<0>();
        }
        __syncthreads();

        const uint32_t abase = sbase + c * STAGE_BYTES;
        const uint32_t bbase = abase + MAT_BYTES;

        // chunk covers 128 fp8 K-elements = 4 x k32 MMA steps
        #pragma unroll
        for (int ks = 0; ks < 4; ++ks) {
            uint32_t afr[2][4];
            #pragma unroll
            for (int mf = 0; mf < 2; ++mf) {
                int r  = warp_m + mf * 16 + (lane & 15);
                int kg = 2 * ks + (lane >> 4);
                LDSM_X4(afr[mf], abase + sw_off(r, kg));
            }
            uint32_t bfr[4][4];
            #pragma unroll
            for (int nb = 0; nb < 4; ++nb) {
                int n  = warp_n + nb * 16 + ((lane >> 4) << 3) + (lane & 7);
                int kg = 2 * ks + ((lane >> 3) & 1);
                LDSM_X4(bfr[nb], bbase + sw_off(n, kg));
            }
            #pragma unroll
            for (int mf = 0; mf < 2; ++mf)
                #pragma unroll
                for (int nb = 0; nb < 4; ++nb) {
                    MMA16832(acc[mf][2 * nb    ], afr[mf], bfr[nb][0], bfr[nb][1]);
                    MMA16832(acc[mf][2 * nb + 1], afr[mf], bfr[nb][2], bfr[nb][3]);
                }
        }
        __syncthreads();
    }

    // --- Epilogue (same output layout as bf16 m16n8k16) ---
    float rs[4] = {0.f, 0.f, 0.f, 0.f};
    float cs[8][2];
    #pragma unroll
    for (int nf = 0; nf < 8; ++nf) { cs[nf][0] = 0.f; cs[nf][1] = 0.f; }

    #pragma unroll
    for (int mf = 0; mf < 2; ++mf)
        #pragma unroll
        for (int nf = 0; nf < 8; ++nf) {
            float e0 = fast_exp2(acc[mf][nf][0]);
            float e1 = fast_exp2(acc[mf][nf][1]);
            float e2 = fast_exp2(acc[mf][nf][2]);
            float e3 = fast_exp2(acc[mf][nf][3]);
            rs[mf * 2 + 0] += e0 + e1;
            rs[mf * 2 + 1] += e2 + e3;
            cs[nf][0] += e0 + e2;
            cs[nf][1] += e1 + e3;
        }

    #pragma unroll
    for (int o = 1; o < 4; o <<= 1)
        #pragma unroll
        for (int q = 0; q < 4; ++q)
            rs[q] += __shfl_xor_sync(0xffffffffu, rs[q], o);
    if ((lane & 3) == 0) {
        int g    = lane >> 2;
        int slot = 2 * y + (warp & 1);
        g_rowpart[(size_t)(row0 + warp_m +  0 + g) * NSLOTS + slot] = rs[0];
        g_rowpart[(size_t)(row0 + warp_m +  8 + g) * NSLOTS + slot] = rs[1];
        g_rowpart[(size_t)(row0 + warp_m + 16 + g) * NSLOTS + slot] = rs[2];
        g_rowpart[(size_t)(row0 + warp_m + 24 + g) * NSLOTS + slot] = rs[3];
    }

    if (x != y) {
        #pragma unroll
        for (int o = 4; o < 32; o <<= 1)
            #pragma unroll
            for (int nf = 0; nf < 8; ++nf) {
                cs[nf][0] += __shfl_xor_sync(0xffffffffu, cs[nf][0], o);
                cs[nf][1] += __shfl_xor_sync(0xffffffffu, cs[nf][1], o);
            }
        float* cw = reinterpret_cast<float*>(smem + CW_OFF);
        if (lane < 4) {
            #pragma unroll
            for (int nf = 0; nf < 8; ++nf) {
                cw[warp * 64 + nf * 8 + 2 * lane    ] = cs[nf][0];
                cw[warp * 64 + nf * 8 + 2 * lane + 1] = cs[nf][1];
            }
        }
        __syncthreads();
        int j  = tid & 63;
        int h  = (tid >> 6) & 1;
        int mp = tid >> 7;
        float v = cw[(h + 4 * mp) * 64 + j] + cw[(h + 4 * mp + 2) * 64 + j];
        g_rowpart[(size_t)(col0 + h * 64 + j) * NSLOTS + (2 * x + mp)] = v;
    }
}

// ---------------------------------------------------------------------------
// Kernel 3: per-row loss term + fused deterministic final reduction.
// diag/pos recomputed in fp32 from the SAME fp8 values the MMA consumed.
// ---------------------------------------------------------------------------
__global__ __launch_bounds__(256) void rowloss_kernel(float* __restrict__ out) {
    __shared__ float wsum[8];
    __shared__ int s_last;
    int w    = threadIdx.x >> 5;
    int lane = threadIdx.x & 31;
    int row  = blockIdx.x * 8 + w;
    int prow = (row < 4096) ? row + 4096 : row - 4096;

    const float* pp = g_rowpart + (size_t)row * NSLOTS;
    float se = pp[lane] + pp[lane + 32] + pp[lane + 64] + pp[lane + 96];

    uint2 av = reinterpret_cast<const uint2*>(g_zb8 + (size_t)row  * DK)[lane];
    uint2 bv = reinterpret_cast<const uint2*>(g_zb8 + (size_t)prow * DK)[lane];
    float diag = 0.f, pos = 0.f;                 // scaled units
    const uint32_t aw[2] = {av.x, av.y};
    const uint32_t bw[2] = {bv.x, bv.y};
    #pragma unroll
    for (int k = 0; k < 2; ++k)
        #pragma unroll
        for (int b = 0; b < 4; ++b) {
            float a = fp8_to_f32((aw[k] >> (8 * b)) & 0xFF);
            float c = fp8_to_f32((bw[k] >> (8 * b)) & 0xFF);
            diag += a * a;
            pos  += a * c;
        }
    #pragma unroll
    for (int o = 16; o; o >>= 1) {
        se   += __shfl_xor_sync(0xffffffffu, se,   o);
        diag += __shfl_xor_sync(0xffffffffu, diag, o);
        pos  += __shfl_xor_sync(0xffffffffu, pos,  o);
    }
    if (lane == 0) {
        float sv = se - fast_exp2(diag);        // same exp formula -> cancels
        wsum[w] = __logf(sv) - pos * 0.6931471805599453f;
    }
    __syncthreads();
    if (threadIdx.x == 0) {
        float s = 0.f;
        #pragma unroll
        for (int i = 0; i < 8; ++i) s += wsum[i];
        g_partial[blockIdx.x] = s;
        __threadfence();
        s_last = (atomicAdd(&g_done, 1) == (int)gridDim.x - 1);
    }
    __syncthreads();

    if (s_last) {
        float s = g_partial[threadIdx.x]
                + g_partial[threadIdx.x + 256]
                + g_partial[threadIdx.x + 512]
                + g_partial[threadIdx.x + 768];
        __shared__ float red[256];
        red[threadIdx.x] = s;
        __syncthreads();
        #pragma unroll
        for (int o = 128; o; o >>= 1) {
            if (threadIdx.x < o) red[threadIdx.x] += red[threadIdx.x + o];
            __syncthreads();
        }
        if (threadIdx.x == 0) out[0] = red[0] * (1.0f / (float)N_TOTAL);
    }
}

// ---------------------------------------------------------------------------
extern "C" void kernel_launch(void* const* d_in, const int* in_sizes, int n_in,
                              void* d_out, int out_size)
{
    const float* zi = (const float*)d_in[0];
    const float* zj = (const float*)d_in[1];
    float* out = (float*)d_out;

    cudaFuncSetAttribute(simexp_kernel,
                         cudaFuncAttributeMaxDynamicSharedMemorySize, SMEM_BYTES);

    normalize_kernel<<<1024, 256>>>(zi, zj);
    simexp_kernel<<<NTRI, 256, SMEM_BYTES>>>();
    rowloss_kernel<<<1024, 256>>>(out);
}

// round 9
// speedup vs baseline: 1.0758x; 1.0758x over previous
#include <cuda_runtime.h>
#include <cuda_bf16.h>
#include <cstdint>

// ===========================================================================
// NT-Xent (SimCLR) loss, B=4096, D=256, T=0.5  ->  N=8192 rows, K=256.
//
// R8 = R6 (proven 59.9us bf16 path) with:
//   * 3-stage cp.async pipeline, ONE __syncthreads per chunk (was 2)
//   * normalize kernel with 2 rows/warp (MLP 2 -> 4)
// FP8 path from R7 reverted: measured slower (64.0us) -- QMMA on the plain
// compute_103 mma.sync path does not beat bf16 HMMA.
//
// Triangle trick: exp(2*sim) symmetric -> 2080 upper 128x128 tiles; off-diag
// tiles emit row-sums AND col-sums. Logit scale folded into inputs
// (zb = z_hat * sqrt(2*log2 e)) so epilogue exp = bare ex2.approx.
// Diagonal subtracted later with the SAME formula (cancels to rounding).
// ===========================================================================

#define N_TOTAL 8192
#define DK      256
#define TILE    128
#define NTILES  64
#define NSLOTS  (NTILES * 2)                    // 128 partial slots per row
#define NTRI    (NTILES * (NTILES + 1) / 2)     // 2080 triangle tiles

#define SCALE_S 1.6986435987381852f             // sqrt(2*log2(e))

__device__ __nv_bfloat16 g_zb[(size_t)N_TOTAL * DK];        // 4 MB
__device__ float g_rowpart[(size_t)N_TOTAL * NSLOTS];       // 4 MB
__device__ float g_partial[1024];
__device__ int   g_done;

// ---------------------------------------------------------------------------
__device__ __forceinline__ uint32_t smem_u32(const void* p) {
    uint32_t a;
    asm("{ .reg .u64 t; cvta.to.shared.u64 t, %1; cvt.u32.u64 %0, t; }"
        : "=r"(a) : "l"(p));
    return a;
}

__device__ __forceinline__ float fast_exp2(float x) {
    float y;
    asm("ex2.approx.f32 %0, %1;" : "=f"(y) : "f"(x));
    return y;
}

#define LDSM_X4(r, addr) \
    asm volatile("ldmatrix.sync.aligned.m8n8.x4.shared.b16 {%0,%1,%2,%3}, [%4];" \
        : "=r"((r)[0]), "=r"((r)[1]), "=r"((r)[2]), "=r"((r)[3]) : "r"(addr))

#define MMA16816(c, a, b0v, b1v) \
    asm volatile("mma.sync.aligned.m16n8k16.row.col.f32.bf16.bf16.f32 " \
        "{%0,%1,%2,%3}, {%4,%5,%6,%7}, {%8,%9}, {%0,%1,%2,%3};" \
        : "+f"((c)[0]), "+f"((c)[1]), "+f"((c)[2]), "+f"((c)[3]) \
        : "r"((a)[0]), "r"((a)[1]), "r"((a)[2]), "r"((a)[3]), \
          "r"(b0v), "r"(b1v))

__device__ __forceinline__ void cp16(uint32_t saddr, const void* gptr) {
    uint64_t g;
    asm volatile("cvta.to.global.u64 %0, %1;" : "=l"(g) : "l"(gptr));
    asm volatile("cp.async.cg.shared.global [%0], [%1], 16;"
                 :: "r"(saddr), "l"(g) : "memory");
}
template <int N>
__device__ __forceinline__ void cp_wait() {
    asm volatile("cp.async.wait_group %0;" :: "n"(N) : "memory");
}
__device__ __forceinline__ void cp_commit() {
    asm volatile("cp.async.commit_group;" ::: "memory");
}

// ---------------------------------------------------------------------------
// Kernel 1: normalize rows -> bf16 (pre-scaled by SCALE_S), reset done ctr.
// 2 rows per warp, all 4 float4 loads issued up front (MLP=4).
// ---------------------------------------------------------------------------
__global__ __launch_bounds__(256) void normalize_kernel(
    const float* __restrict__ zi, const float* __restrict__ zj)
{
    if (blockIdx.x == 0 && threadIdx.x == 0) g_done = 0;
    int w    = threadIdx.x >> 5;
    int lane = threadIdx.x & 31;
    int row0 = blockIdx.x * 16 + w * 2;          // this warp: row0, row0+1
    const float* s0 = (row0     < 4096) ? zi + (size_t)row0 * DK
                                        : zj + (size_t)(row0 - 4096) * DK;
    const float* s1 = (row0 + 1 < 4096) ? zi + (size_t)(row0 + 1) * DK
                                        : zj + (size_t)(row0 + 1 - 4096) * DK;
    float4 a0 = reinterpret_cast<const float4*>(s0)[lane * 2];
    float4 a1 = reinterpret_cast<const float4*>(s0)[lane * 2 + 1];
    float4 b0 = reinterpret_cast<const float4*>(s1)[lane * 2];
    float4 b1 = reinterpret_cast<const float4*>(s1)[lane * 2 + 1];

    float sa = a0.x * a0.x + a0.y * a0.y + a0.z * a0.z + a0.w * a0.w
             + a1.x * a1.x + a1.y * a1.y + a1.z * a1.z + a1.w * a1.w;
    float sb = b0.x * b0.x + b0.y * b0.y + b0.z * b0.z + b0.w * b0.w
             + b1.x * b1.x + b1.y * b1.y + b1.z * b1.z + b1.w * b1.w;
    #pragma unroll
    for (int o = 16; o; o >>= 1) {
        sa += __shfl_xor_sync(0xffffffffu, sa, o);
        sb += __shfl_xor_sync(0xffffffffu, sb, o);
    }
    float ra = rsqrtf(sa) * SCALE_S;
    float rb = rsqrtf(sb) * SCALE_S;

    __nv_bfloat162 p0 = __floats2bfloat162_rn(a0.x * ra, a0.y * ra);
    __nv_bfloat162 p1 = __floats2bfloat162_rn(a0.z * ra, a0.w * ra);
    __nv_bfloat162 p2 = __floats2bfloat162_rn(a1.x * ra, a1.y * ra);
    __nv_bfloat162 p3 = __floats2bfloat162_rn(a1.z * ra, a1.w * ra);
    uint4 oa;
    oa.x = *reinterpret_cast<uint32_t*>(&p0);
    oa.y = *reinterpret_cast<uint32_t*>(&p1);
    oa.z = *reinterpret_cast<uint32_t*>(&p2);
    oa.w = *reinterpret_cast<uint32_t*>(&p3);
    reinterpret_cast<uint4*>(g_zb + (size_t)row0 * DK)[lane] = oa;

    p0 = __floats2bfloat162_rn(b0.x * rb, b0.y * rb);
    p1 = __floats2bfloat162_rn(b0.z * rb, b0.w * rb);
    p2 = __floats2bfloat162_rn(b1.x * rb, b1.y * rb);
    p3 = __floats2bfloat162_rn(b1.z * rb, b1.w * rb);
    uint4 ob;
    ob.x = *reinterpret_cast<uint32_t*>(&p0);
    ob.y = *reinterpret_cast<uint32_t*>(&p1);
    ob.z = *reinterpret_cast<uint32_t*>(&p2);
    ob.w = *reinterpret_cast<uint32_t*>(&p3);
    reinterpret_cast<uint4*>(g_zb + (size_t)(row0 + 1) * DK)[lane] = ob;
}

// ---------------------------------------------------------------------------
// Kernel 2: upper-triangle 128x128 HMMA tiles + exp row/col sums.
// 1D grid of 2080 CTAs; CTA t -> tile (x, y), y >= x.
// 256 threads (8 warps, 4(M) x 2(N), warp tile 32x64).
// K=256 in 4 chunks of 64 via 3-STAGE cp.async (96 KB smem, 2 CTAs/SM),
// prefetch distance 2, ONE __syncthreads per chunk.
// ---------------------------------------------------------------------------
#define KCHUNK      64
#define MAT_BYTES   (TILE * KCHUNK * 2)          // 16384
#define STAGE_BYTES (2 * MAT_BYTES)              // 32768
#define NSTAGE      3
#define CW_OFF      (NSTAGE * STAGE_BYTES)       // 98304
#define SMEM_BYTES  (CW_OFF + 2048)              // 100352

__device__ __forceinline__ uint32_t sw_off(int r, int kg) {
    return (uint32_t)(r * 128 + ((kg ^ (r & 7)) << 4));
}

__device__ __forceinline__ void prefetch_chunk(
    uint32_t sbase, int stage, int row0, int col0, int chunk, int tid)
{
    #pragma unroll
    for (int i = 0; i < 8; ++i) {
        int v   = tid + i * 256;         // 0..2047
        int mat = v >> 10;               // 0 = A, 1 = B
        int r   = (v >> 3) & 127;
        int kg  = v & 7;
        int grow = (mat ? col0 : row0) + r;
        const __nv_bfloat16* g = g_zb + (size_t)grow * DK + chunk * KCHUNK + kg * 8;
        uint32_t s = sbase + stage * STAGE_BYTES + mat * MAT_BYTES + sw_off(r, kg);
        cp16(s, g);
    }
    cp_commit();
}

__global__ __launch_bounds__(256, 2) void simexp_kernel() {
    extern __shared__ char smem[];
    const uint32_t sbase = smem_u32(smem);
    const int tid  = threadIdx.x;
    const int warp = tid >> 5;
    const int lane = tid & 31;

    // --- decode linear tile id -> (x, y) with y >= x; start(x)=x*(129-x)/2 ---
    const int t = blockIdx.x;
    int x = __float2int_rd((129.0f - sqrtf(16641.0f - 8.0f * (float)t)) * 0.5f);
    if (x > 63) x = 63;
    while (x > 0 && x * (129 - x) / 2 > t) --x;
    while ((x + 1) * (129 - (x + 1)) / 2 <= t) ++x;
    const int y = x + (t - x * (129 - x) / 2);

    const int row0 = x * TILE;
    const int col0 = y * TILE;
    const int warp_m = (warp >> 1) * 32;
    const int warp_n = (warp & 1) * 64;

    float acc[2][8][4];
    #pragma unroll
    for (int mf = 0; mf < 2; ++mf)
        #pragma unroll
        for (int nf = 0; nf < 8; ++nf)
            #pragma unroll
            for (int q = 0; q < 4; ++q) acc[mf][nf][q] = 0.f;

    prefetch_chunk(sbase, 0, row0, col0, 0, tid);
    prefetch_chunk(sbase, 1, row0, col0, 1, tid);

    #pragma unroll
    for (int c = 0; c < 4; ++c) {
        if (c < 3) { cp_wait<1>(); } else { cp_wait<0>(); }
        __syncthreads();                         // chunk c resident; all warps
                                                 // done with chunk c-1 (so the
                                                 // c+2 prefetch below is safe)
        if (c + 2 < 4)
            prefetch_chunk(sbase, (c + 2) % NSTAGE, row0, col0, c + 2, tid);

        const uint32_t abase = sbase + (c % NSTAGE) * STAGE_BYTES;
        const uint32_t bbase = abase + MAT_BYTES;

        #pragma unroll
        for (int ks = 0; ks < 4; ++ks) {
            uint32_t afr[2][4];
            #pragma unroll
            for (int mf = 0; mf < 2; ++mf) {
                int r  = warp_m + mf * 16 + (lane & 15);
                int kg = 2 * ks + (lane >> 4);
                LDSM_X4(afr[mf], abase + sw_off(r, kg));
            }
            uint32_t bfr[4][4];
            #pragma unroll
            for (int nb = 0; nb < 4; ++nb) {
                int n  = warp_n + nb * 16 + ((lane >> 4) << 3) + (lane & 7);
                int kg = 2 * ks + ((lane >> 3) & 1);
                LDSM_X4(bfr[nb], bbase + sw_off(n, kg));
            }
            #pragma unroll
            for (int mf = 0; mf < 2; ++mf)
                #pragma unroll
                for (int nb = 0; nb < 4; ++nb) {
                    MMA16816(acc[mf][2 * nb    ], afr[mf], bfr[nb][0], bfr[nb][1]);
                    MMA16816(acc[mf][2 * nb + 1], afr[mf], bfr[nb][2], bfr[nb][3]);
                }
        }
    }

    // --- Epilogue ---
    float rs[4] = {0.f, 0.f, 0.f, 0.f};
    float cs[8][2];
    #pragma unroll
    for (int nf = 0; nf < 8; ++nf) { cs[nf][0] = 0.f; cs[nf][1] = 0.f; }

    #pragma unroll
    for (int mf = 0; mf < 2; ++mf)
        #pragma unroll
        for (int nf = 0; nf < 8; ++nf) {
            float e0 = fast_exp2(acc[mf][nf][0]);
            float e1 = fast_exp2(acc[mf][nf][1]);
            float e2 = fast_exp2(acc[mf][nf][2]);
            float e3 = fast_exp2(acc[mf][nf][3]);
            rs[mf * 2 + 0] += e0 + e1;
            rs[mf * 2 + 1] += e2 + e3;
            cs[nf][0] += e0 + e2;
            cs[nf][1] += e1 + e3;
        }

    #pragma unroll
    for (int o = 1; o < 4; o <<= 1)
        #pragma unroll
        for (int q = 0; q < 4; ++q)
            rs[q] += __shfl_xor_sync(0xffffffffu, rs[q], o);
    if ((lane & 3) == 0) {
        int g    = lane >> 2;
        int slot = 2 * y + (warp & 1);
        g_rowpart[(size_t)(row0 + warp_m +  0 + g) * NSLOTS + slot] = rs[0];
        g_rowpart[(size_t)(row0 + warp_m +  8 + g) * NSLOTS + slot] = rs[1];
        g_rowpart[(size_t)(row0 + warp_m + 16 + g) * NSLOTS + slot] = rs[2];
        g_rowpart[(size_t)(row0 + warp_m + 24 + g) * NSLOTS + slot] = rs[3];
    }

    if (x != y) {
        #pragma unroll
        for (int o = 4; o < 32; o <<= 1)
            #pragma unroll
            for (int nf = 0; nf < 8; ++nf) {
                cs[nf][0] += __shfl_xor_sync(0xffffffffu, cs[nf][0], o);
                cs[nf][1] += __shfl_xor_sync(0xffffffffu, cs[nf][1], o);
            }
        float* cw = reinterpret_cast<float*>(smem + CW_OFF);
        if (lane < 4) {
            #pragma unroll
            for (int nf = 0; nf < 8; ++nf) {
                cw[warp * 64 + nf * 8 + 2 * lane    ] = cs[nf][0];
                cw[warp * 64 + nf * 8 + 2 * lane + 1] = cs[nf][1];
            }
        }
        __syncthreads();
        int j  = tid & 63;
        int h  = (tid >> 6) & 1;
        int mp = tid >> 7;
        float v = cw[(h + 4 * mp) * 64 + j] + cw[(h + 4 * mp + 2) * 64 + j];
        g_rowpart[(size_t)(col0 + h * 64 + j) * NSLOTS + (2 * x + mp)] = v;
    }
}

// ---------------------------------------------------------------------------
// Kernel 3: per-row loss term + fused deterministic final reduction
// ---------------------------------------------------------------------------
__global__ __launch_bounds__(256) void rowloss_kernel(float* __restrict__ out) {
    __shared__ float wsum[8];
    __shared__ int s_last;
    int w    = threadIdx.x >> 5;
    int lane = threadIdx.x & 31;
    int row  = blockIdx.x * 8 + w;
    int prow = (row < 4096) ? row + 4096 : row - 4096;

    const float* pp = g_rowpart + (size_t)row * NSLOTS;
    float se = pp[lane] + pp[lane + 32] + pp[lane + 64] + pp[lane + 96];

    uint4 av4 = reinterpret_cast<const uint4*>(g_zb + (size_t)row  * DK)[lane];
    uint4 bv4 = reinterpret_cast<const uint4*>(g_zb + (size_t)prow * DK)[lane];
    float diag = 0.f, pos = 0.f;                 // scaled units
    const uint32_t* au = &av4.x;
    const uint32_t* bu = &bv4.x;
    #pragma unroll
    for (int k = 0; k < 4; ++k) {
        __nv_bfloat162 a2 = *reinterpret_cast<const __nv_bfloat162*>(&au[k]);
        __nv_bfloat162 b2 = *reinterpret_cast<const __nv_bfloat162*>(&bu[k]);
        float ax = __bfloat162float(a2.x), ay = __bfloat162float(a2.y);
        float bx = __bfloat162float(b2.x), by = __bfloat162float(b2.y);
        diag += ax * ax + ay * ay;
        pos  += ax * bx + ay * by;
    }
    #pragma unroll
    for (int o = 16; o; o >>= 1) {
        se   += __shfl_xor_sync(0xffffffffu, se,   o);
        diag += __shfl_xor_sync(0xffffffffu, diag, o);
        pos  += __shfl_xor_sync(0xffffffffu, pos,  o);
    }
    if (lane == 0) {
        float sv = se - fast_exp2(diag);        // same exp formula -> cancels
        wsum[w] = __logf(sv) - pos * 0.6931471805599453f;
    }
    __syncthreads();
    if (threadIdx.x == 0) {
        float s = 0.f;
        #pragma unroll
        for (int i = 0; i < 8; ++i) s += wsum[i];
        g_partial[blockIdx.x] = s;
        __threadfence();
        s_last = (atomicAdd(&g_done, 1) == (int)gridDim.x - 1);
    }
    __syncthreads();

    if (s_last) {
        float s = g_partial[threadIdx.x]
                + g_partial[threadIdx.x + 256]
                + g_partial[threadIdx.x + 512]
                + g_partial[threadIdx.x + 768];
        __shared__ float red[256];
        red[threadIdx.x] = s;
        __syncthreads();
        #pragma unroll
        for (int o = 128; o; o >>= 1) {
            if (threadIdx.x < o) red[threadIdx.x] += red[threadIdx.x + o];
            __syncthreads();
        }
        if (threadIdx.x == 0) out[0] = red[0] * (1.0f / (float)N_TOTAL);
    }
}

// ---------------------------------------------------------------------------
extern "C" void kernel_launch(void* const* d_in, const int* in_sizes, int n_in,
                              void* d_out, int out_size)
{
    const float* zi = (const float*)d_in[0];
    const float* zj = (const float*)d_in[1];
    float* out = (float*)d_out;

    cudaFuncSetAttribute(simexp_kernel,
                         cudaFuncAttributeMaxDynamicSharedMemorySize, SMEM_BYTES);

    normalize_kernel<<<512, 256>>>(zi, zj);
    simexp_kernel<<<NTRI, 256, SMEM_BYTES>>>();
    rowloss_kernel<<<1024, 256>>>(out);
}